// round 16
// baseline (speedup 1.0000x reference)
#include <cuda_runtime.h>
#include <stdint.h>

// out[i, 0:8] = params[idx[i]] * xs[i, 0:8]
// xs: float32 [N, 8]; idx: int32 [N]; params: float32 [V]; out: float32 [N, 8]
// N = 4194304, V = 1048576.
//
// Champion data path + Blackwell 256-bit vector memory ops: one thread per
// row, a single ld.global.cs.v8.b32 (32B) covers the whole row and a single
// st.global.cs.v8.b32 writes it -> half the streaming instructions of the
// float4 scheme, identical DRAM traffic, still fully dense 1024B/warp.
// Gather stays L2-only (__ldcg, table L2-resident); streams evict-first.

#define N_ROWS  4194304
#define UNROLL  2
#define THREADS 256
#define BLOCKS  (N_ROWS / (UNROLL * THREADS))   // 8192

struct __align__(32) f32x8 { float v[8]; };

__device__ __forceinline__ void ldg_cs_256(const f32x8* p, float* d) {
    asm volatile(
        "ld.global.cs.v8.b32 {%0,%1,%2,%3,%4,%5,%6,%7}, [%8];"
        : "=f"(d[0]), "=f"(d[1]), "=f"(d[2]), "=f"(d[3]),
          "=f"(d[4]), "=f"(d[5]), "=f"(d[6]), "=f"(d[7])
        : "l"(p));
}

__device__ __forceinline__ void stg_cs_256(f32x8* p, const float* d) {
    asm volatile(
        "st.global.cs.v8.b32 [%0], {%1,%2,%3,%4,%5,%6,%7,%8};"
        :: "l"(p),
           "f"(d[0]), "f"(d[1]), "f"(d[2]), "f"(d[3]),
           "f"(d[4]), "f"(d[5]), "f"(d[6]), "f"(d[7])
        : "memory");
}

__global__ __launch_bounds__(THREADS) void gather_mul_kernel(
    const f32x8* __restrict__ xs,      // [N] rows
    const int*   __restrict__ idx,     // [N] int32
    const float* __restrict__ params,  // [V]
    f32x8*       __restrict__ out)     // [N] rows
{
    const int t = blockIdx.x * THREADS + threadIdx.x;
    const int S = BLOCKS * THREADS;    // 2M rows per sweep

    // 1) Batch index loads (dense 4B lane-contiguous).
    int j[UNROLL];
#pragma unroll
    for (int k = 0; k < UNROLL; k++)
        j[k] = __ldcs(idx + t + k * S);

    // 2) Batch param gathers: L2-only, table is L2-resident.
    float p[UNROLL];
#pragma unroll
    for (int k = 0; k < UNROLL; k++)
        p[k] = __ldcg(params + j[k]);

    // 3) Batch full-row loads: one 256-bit LDG per row, 32B lane-contiguous.
    float x[UNROLL][8];
#pragma unroll
    for (int k = 0; k < UNROLL; k++)
        ldg_cs_256(xs + t + k * S, x[k]);

    // 4) Multiply + one 256-bit streaming store per row.
#pragma unroll
    for (int k = 0; k < UNROLL; k++) {
        float o[8];
#pragma unroll
        for (int e = 0; e < 8; e++)
            o[e] = p[k] * x[k][e];
        stg_cs_256(out + t + k * S, o);
    }
}

extern "C" void kernel_launch(void* const* d_in, const int* in_sizes, int n_in,
                              void* d_out, int out_size)
{
    const f32x8* xs     = (const f32x8*)d_in[0];
    const int*   idx    = (const int*)d_in[1];
    const float* params = (const float*)d_in[2];
    f32x8*       out    = (f32x8*)d_out;

    gather_mul_kernel<<<BLOCKS, THREADS>>>(xs, idx, params, out);
}

// round 17
// speedup vs baseline: 1.0095x; 1.0095x over previous
#include <cuda_runtime.h>
#include <stdint.h>

// out[i, 0:8] = params[idx[i]] * xs[i, 0:8]
// xs: float32 [N, 8]; idx: int32 [N]; params: float32 [V]; out: float32 [N, 8]
// N = 4194304, V = 1048576.
//
// FINAL kernel — best measured across 15 variants (43.1 us kernel, 5.65 TB/s
// = 71% of spec HBM, bench 47.1 us, rel_err 0.0). Structure: direct LDG/STG,
// 2 threads per row so every streaming access is a dense 16B lane-contiguous
// wavefront; lane pairs broadcast the idx/param access. Streams evict-first
// (__ldcs/__stcs) keep the 4 MB param table L2-resident; gather is L2-only
// (__ldcg, no L1 reuse).
// Proven non-binding: occupancy (42-83% identical), unroll 4 vs 8, DRAM page
// layout (3 variants), L2 evict_last pinning, persistent single-wave grid,
// 256-bit v8.b32 loads/stores (halved L1 issue, dur flat -> DRAM-sched wall).
// Proven worse: TMA/smem staging (-30..65%), write-through stores (-3..6%).
// Remaining gap to spec BW is irreducible: random gather sectors + mixed
// read/write DRAM scheduling. Traffic is at the compulsory minimum.

#define N_ROWS  4194304
#define ITEMS   (2 * N_ROWS)                   // 8M float4 half-rows
#define UNROLL  4
#define THREADS 256
#define BLOCKS  (ITEMS / (UNROLL * THREADS))   // 8192

__global__ __launch_bounds__(THREADS) void gather_mul_kernel(
    const float4* __restrict__ xs,     // [ITEMS]
    const int*    __restrict__ idx,    // [N] int32
    const float*  __restrict__ params, // [V]
    float4*       __restrict__ out)    // [ITEMS]
{
    const int t = blockIdx.x * THREADS + threadIdx.x;
    const int S = BLOCKS * THREADS;    // 2M items per sweep

    // 1) Batch index loads (lane pairs share an address -> broadcast).
    int j[UNROLL];
#pragma unroll
    for (int k = 0; k < UNROLL; k++)
        j[k] = __ldcs(idx + ((t + k * S) >> 1));

    // 2) Batch param gathers: L2-only, table is L2-resident.
    float p[UNROLL];
#pragma unroll
    for (int k = 0; k < UNROLL; k++)
        p[k] = __ldcg(params + j[k]);

    // 3) Batch xs half-row loads: 16B lane-contiguous, evict-first.
    float4 x[UNROLL];
#pragma unroll
    for (int k = 0; k < UNROLL; k++)
        x[k] = __ldcs(xs + t + k * S);

    // 4) Multiply + streaming stores (evict-first).
#pragma unroll
    for (int k = 0; k < UNROLL; k++) {
        float4 o;
        o.x = p[k] * x[k].x;
        o.y = p[k] * x[k].y;
        o.z = p[k] * x[k].z;
        o.w = p[k] * x[k].w;
        __stcs(out + t + k * S, o);
    }
}

extern "C" void kernel_launch(void* const* d_in, const int* in_sizes, int n_in,
                              void* d_out, int out_size)
{
    const float4* xs     = (const float4*)d_in[0];
    const int*    idx    = (const int*)d_in[1];
    const float*  params = (const float*)d_in[2];
    float4*       out    = (float4*)d_out;

    gather_mul_kernel<<<BLOCKS, THREADS>>>(xs, idx, params, out);
}